// round 10
// baseline (speedup 1.0000x reference)
#include <cuda_runtime.h>
#include <cuda_fp16.h>
#include <cstdint>
#include <cstddef>

// FFN: out = relu(x @ w1 + b1) @ w2 + b2
// R9: single-term fp16 mma.sync at the measured 16.4cyc/SMSP HMMA rate.
// - BKT=64, 2-stage cp.async (fewer barriers per MMA), 2 CTAs/SM.
// - GEMM2 split-K=4 (2048 CTAs -> clean 6.9 waves) + deterministic add kernel.

#define M_TOTAL 8192
#define D_DIM   1024
#define W_DIM   4096

// ---- device scratch ----
__device__ __half g_xh[(size_t)M_TOTAL * D_DIM];
__device__ __half g_hh[(size_t)M_TOTAL * W_DIM];
__device__ __half g_w1t[(size_t)W_DIM * D_DIM];
__device__ __half g_w2t[(size_t)D_DIM * W_DIM];
__device__ float  g_part[(size_t)4 * M_TOTAL * D_DIM];   // split-K partials, 128MB

// ---- helpers ----
__device__ __forceinline__ uint32_t smem_u32(const void* p) {
    uint32_t a;
    asm("{ .reg .u64 t; cvta.to.shared.u64 t, %1; cvt.u32.u64 %0, t; }" : "=r"(a) : "l"(p));
    return a;
}
__device__ __forceinline__ void cpasync16(uint32_t dst, const void* src) {
    asm volatile("cp.async.cg.shared.global [%0], [%1], 16;" :: "r"(dst), "l"(src));
}
__device__ __forceinline__ void cp_commit() {
    asm volatile("cp.async.commit_group;" ::: "memory");
}
__device__ __forceinline__ void cp_wait1() {
    asm volatile("cp.async.wait_group 1;" ::: "memory");
}
__device__ __forceinline__ void ldsm4(uint32_t* r, uint32_t addr) {
    asm volatile("ldmatrix.sync.aligned.m8n8.x4.shared.b16 {%0,%1,%2,%3}, [%4];"
                 : "=r"(r[0]), "=r"(r[1]), "=r"(r[2]), "=r"(r[3]) : "r"(addr));
}
__device__ __forceinline__ void mma16816(float* c, const uint32_t* a, uint32_t b0, uint32_t b1) {
    asm volatile("mma.sync.aligned.m16n8k16.row.col.f32.f16.f16.f32 "
                 "{%0,%1,%2,%3}, {%4,%5,%6,%7}, {%8,%9}, {%0,%1,%2,%3};"
                 : "+f"(c[0]), "+f"(c[1]), "+f"(c[2]), "+f"(c[3])
                 : "r"(a[0]), "r"(a[1]), "r"(a[2]), "r"(a[3]), "r"(b0), "r"(b1));
}

// ---- prepass: fp32 -> fp16 ----
__global__ void cvt_half_kernel(const float* __restrict__ X,
                                __half* __restrict__ Xh, size_t n4) {
    size_t i = (size_t)blockIdx.x * blockDim.x + threadIdx.x;
    if (i >= n4) return;
    float4 v = ((const float4*)X)[i];
    uint32_t p0 = ((uint32_t)__half_as_ushort(__float2half_rn(v.y)) << 16)
                 | __half_as_ushort(__float2half_rn(v.x));
    uint32_t p1 = ((uint32_t)__half_as_ushort(__float2half_rn(v.w)) << 16)
                 | __half_as_ushort(__float2half_rn(v.z));
    ((uint2*)Xh)[i] = make_uint2(p0, p1);
}

// ---- prepass: W [K,N] fp32 -> W^T [N,K] fp16 ----
__global__ void transpose_half_kernel(const float* __restrict__ W,
                                      __half* __restrict__ T,
                                      int K, int N) {
    __shared__ float t[32][33];
    int n0 = blockIdx.x * 32, k0 = blockIdx.y * 32;
    int tx = threadIdx.x, ty = threadIdx.y;
    #pragma unroll
    for (int j = 0; j < 4; j++)
        t[ty + 8 * j][tx] = W[(size_t)(k0 + ty + 8 * j) * N + n0 + tx];
    __syncthreads();
    #pragma unroll
    for (int j = 0; j < 4; j++) {
        float v = t[tx][ty + 8 * j];
        T[(size_t)(n0 + ty + 8 * j) * K + k0 + tx] = __float2half_rn(v);
    }
}

// ---- final reduction: out = p0+p1+p2+p3 + b2 ----
__global__ void addk_kernel(const float* __restrict__ P,
                            const float* __restrict__ bias,
                            float* __restrict__ out, size_t n4, int ncols4) {
    size_t i = (size_t)blockIdx.x * blockDim.x + threadIdx.x;
    if (i >= n4) return;
    const size_t S = (size_t)M_TOTAL * D_DIM / 4;
    float4 a = ((const float4*)P)[i];
    float4 b = ((const float4*)P)[i + S];
    float4 c = ((const float4*)P)[i + 2 * S];
    float4 d = ((const float4*)P)[i + 3 * S];
    float4 bv = ((const float4*)bias)[i % ncols4];
    float4 r;
    r.x = a.x + b.x + c.x + d.x + bv.x;
    r.y = a.y + b.y + c.y + d.y + bv.y;
    r.z = a.z + b.z + c.z + d.z + bv.z;
    r.w = a.w + b.w + c.w + d.w + bv.w;
    ((float4*)out)[i] = r;
}

// ---- main GEMM ----
// CTA tile 128x128x(Ktile), BKT=64 per stage, 2 stages, 256 thr (8 warps, 4x2),
// warp tile 32x64.
#define BMT 128
#define BNT 128
#define BKT 64
#define STAGES 2
#define ROWB 144                   // 64 fp16 = 128B + 16B pad
#define TILE_B (128 * ROWB)        // 18432
#define STAGE_B (2 * TILE_B)       // 36864 (A + B)
#define OFF_A 0
#define OFF_B TILE_B
#define SMEM_DYN (STAGES * STAGE_B)   // 73728 -> 2 CTAs/SM

// G1EPI: true -> bias+relu, fp16 store to Ch. false -> raw fp32 partial to Cf.
template<bool G1EPI>
__global__ __launch_bounds__(256, 2)
void ffn_mma(const __half* __restrict__ A, int lda,
             const __half* __restrict__ B, int ldb,
             int Ktile,
             const float* __restrict__ bias,
             float* __restrict__ Cf,
             __half* __restrict__ Ch,
             int ldc) {
    extern __shared__ char smem[];
    const uint32_t sbase = smem_u32(smem);
    const int tid = threadIdx.x;
    const int lane = tid & 31, wid = tid >> 5;
    const int wm = (wid >> 1) * 32, wn = (wid & 1) * 64;
    const int bm = blockIdx.y * BMT, bn = blockIdx.x * BNT;

    if (!G1EPI) {   // split-K slice offsets
        int z = blockIdx.z;
        A += (size_t)z * 1024;
        B += (size_t)z * 1024;
        Cf += (size_t)z * M_TOTAL * D_DIM;
    }

    const __half* Ab = A + (size_t)bm * lda;
    const __half* Bb = B + (size_t)bn * ldb;

    const int lr = tid >> 1;          // 0..127 (row for both A and B tiles)
    const int lc = (tid & 1) * 4;     // starting 16B chunk (0 or 4)

    const int nIters = Ktile / BKT;

    auto issue_stage = [&](int s) {
        uint32_t dst = sbase + (uint32_t)(s & 1) * STAGE_B;
        int k0 = s * BKT;
        #pragma unroll
        for (int j = 0; j < 4; j++) {
            uint32_t d = dst + (uint32_t)lr * ROWB + (uint32_t)(lc + j) * 16;
            cpasync16(d + OFF_A, Ab + (size_t)lr * lda + k0 + (lc + j) * 8);
            cpasync16(d + OFF_B, Bb + (size_t)lr * ldb + k0 + (lc + j) * 8);
        }
        cp_commit();
    };

    issue_stage(0);

    float acc[2][8][4];
    #pragma unroll
    for (int mi = 0; mi < 2; mi++)
        #pragma unroll
        for (int f = 0; f < 8; f++)
            #pragma unroll
            for (int q = 0; q < 4; q++)
                acc[mi][f][q] = 0.0f;

    const uint32_t arow = (uint32_t)(lane & 15) * ROWB + (uint32_t)(lane >> 4) * 16;

    for (int i = 0; i < nIters; i++) {
        if (i + 1 < nIters) issue_stage(i + 1);
        else cp_commit();             // keep group count exact
        cp_wait1();                   // stage i resident
        __syncthreads();

        uint32_t sa = sbase + (uint32_t)(i & 1) * STAGE_B;

        #pragma unroll
        for (int kk = 0; kk < 4; kk++) {
            uint32_t ah[2][4], bh[4][4];
            uint32_t koff = (uint32_t)kk * 32;
            #pragma unroll
            for (int mi = 0; mi < 2; mi++) {
                uint32_t a = sa + (uint32_t)(wm + mi * 16) * ROWB + arow + koff;
                ldsm4(ah[mi], a + OFF_A);
            }
            #pragma unroll
            for (int nb = 0; nb < 4; nb++) {
                uint32_t a = sa + (uint32_t)(wn + nb * 16) * ROWB + arow + koff;
                ldsm4(bh[nb], a + OFF_B);
            }
            #pragma unroll
            for (int mi = 0; mi < 2; mi++)
                #pragma unroll
                for (int f = 0; f < 8; f++) {
                    int nb = f >> 1, p = f & 1;
                    mma16816(acc[mi][f], ah[mi], bh[nb][p], bh[nb][2 + p]);
                }
        }
        __syncthreads();
    }

    // ---- epilogue ----
    const int g = lane >> 2, t = lane & 3;
    #pragma unroll
    for (int mi = 0; mi < 2; mi++) {
        #pragma unroll
        for (int f = 0; f < 8; f++) {
            int row = bm + wm + mi * 16 + g;
            int col = bn + wn + f * 8 + t * 2;
            float v0 = acc[mi][f][0], v1 = acc[mi][f][1];
            float v2 = acc[mi][f][2], v3 = acc[mi][f][3];
            if (G1EPI) {
                float b0 = __ldg(bias + col), b1 = __ldg(bias + col + 1);
                v0 = fmaxf(v0 + b0, 0.f); v1 = fmaxf(v1 + b1, 0.f);
                v2 = fmaxf(v2 + b0, 0.f); v3 = fmaxf(v3 + b1, 0.f);
                uint32_t pa = ((uint32_t)__half_as_ushort(__float2half_rn(v1)) << 16)
                             | __half_as_ushort(__float2half_rn(v0));
                uint32_t pb = ((uint32_t)__half_as_ushort(__float2half_rn(v3)) << 16)
                             | __half_as_ushort(__float2half_rn(v2));
                *(uint32_t*)(Ch + (size_t)row * ldc + col) = pa;
                *(uint32_t*)(Ch + (size_t)(row + 8) * ldc + col) = pb;
            } else {
                *(float2*)(Cf + (size_t)row * ldc + col) = make_float2(v0, v1);
                *(float2*)(Cf + (size_t)(row + 8) * ldc + col) = make_float2(v2, v3);
            }
        }
    }
}

extern "C" void kernel_launch(void* const* d_in, const int* in_sizes, int n_in,
                              void* d_out, int out_size) {
    const float* x  = (const float*)d_in[0];
    const float* w1 = (const float*)d_in[1];
    const float* b1 = (const float*)d_in[2];
    const float* w2 = (const float*)d_in[3];
    const float* b2 = (const float*)d_in[4];
    float* out = (float*)d_out;

    __half *xh, *hh, *w1t, *w2t;
    float* part;
    cudaGetSymbolAddress((void**)&xh, g_xh);
    cudaGetSymbolAddress((void**)&hh, g_hh);
    cudaGetSymbolAddress((void**)&w1t, g_w1t);
    cudaGetSymbolAddress((void**)&w2t, g_w2t);
    cudaGetSymbolAddress((void**)&part, g_part);

    cudaFuncSetAttribute(ffn_mma<true>,  cudaFuncAttributeMaxDynamicSharedMemorySize, SMEM_DYN);
    cudaFuncSetAttribute(ffn_mma<false>, cudaFuncAttributeMaxDynamicSharedMemorySize, SMEM_DYN);

    // prepasses
    {
        size_t n4 = (size_t)M_TOTAL * D_DIM / 4;
        cvt_half_kernel<<<(unsigned)((n4 + 255) / 256), 256>>>(x, xh, n4);
    }
    transpose_half_kernel<<<dim3(W_DIM / 32, D_DIM / 32), dim3(32, 8)>>>(w1, w1t, D_DIM, W_DIM);
    transpose_half_kernel<<<dim3(D_DIM / 32, W_DIM / 32), dim3(32, 8)>>>(w2, w2t, W_DIM, D_DIM);

    // GEMM1: h = relu(x @ w1 + b1) -> fp16. grid (32, 64), K=1024.
    ffn_mma<true><<<dim3(W_DIM / BNT, M_TOTAL / BMT), 256, SMEM_DYN>>>(
        xh, D_DIM, w1t, D_DIM, D_DIM, b1, nullptr, hh, W_DIM);

    // GEMM2 split-K=4: partials (no bias). grid (8, 64, 4), each slice K=1024.
    ffn_mma<false><<<dim3(D_DIM / BNT, M_TOTAL / BMT, 4), 256, SMEM_DYN>>>(
        hh, W_DIM, w2t, W_DIM, 1024, nullptr, part, nullptr, D_DIM);

    // Reduce partials + bias.
    {
        size_t n4 = (size_t)M_TOTAL * D_DIM / 4;
        addk_kernel<<<(unsigned)((n4 + 255) / 256), 256>>>(part, b2, out, n4, D_DIM / 4);
    }
}